// round 13
// baseline (speedup 1.0000x reference)
#include <cuda_runtime.h>
#include <cuda_bf16.h>
#include <cstdint>
#include <cfloat>

#define S_LEN 2048
#define D_DIM 128
#define QPB   64           // queries per CTA (fine-grain: 1024 CTAs ~ 6.9 waves)
#define NKT   16
#define KTOP  32
#define RSTRIDE 272        // bf16 tile row stride (17*16B): conflict-free ldmatrix

// 512 MB global scratch for the full score matrix [BH=32][2048][2048] fp32
__device__ float g_scores[(size_t)32 * S_LEN * S_LEN];

__device__ __forceinline__ uint32_t smem_u32(const void* p) {
    uint32_t a;
    asm("{ .reg .u64 t; cvta.to.shared.u64 t, %1; cvt.u32.u64 %0, t; }" : "=r"(a) : "l"(p));
    return a;
}

__device__ __forceinline__ void ldsm4(uint32_t& r0, uint32_t& r1, uint32_t& r2, uint32_t& r3,
                                      uint32_t addr) {
    asm volatile("ldmatrix.sync.aligned.m8n8.x4.shared.b16 {%0,%1,%2,%3}, [%4];"
                 : "=r"(r0), "=r"(r1), "=r"(r2), "=r"(r3) : "r"(addr));
}

__device__ __forceinline__ void mma16816(float* c, const uint32_t* a, uint32_t b0, uint32_t b1) {
    asm volatile(
        "mma.sync.aligned.m16n8k16.row.col.f32.bf16.bf16.f32 "
        "{%0,%1,%2,%3}, {%4,%5,%6,%7}, {%8,%9}, {%0,%1,%2,%3};"
        : "+f"(c[0]), "+f"(c[1]), "+f"(c[2]), "+f"(c[3])
        : "r"(a[0]), "r"(a[1]), "r"(a[2]), "r"(a[3]), "r"(b0), "r"(b1));
}

__device__ __forceinline__ void cvt_store(char* smem, uint32_t hi_off, uint32_t lo_off,
                                          int row, int lane, float4 v) {
    __nv_bfloat16 h0 = __float2bfloat16(v.x), h1 = __float2bfloat16(v.y);
    __nv_bfloat16 h2 = __float2bfloat16(v.z), h3 = __float2bfloat16(v.w);
    __nv_bfloat16 l0 = __float2bfloat16(v.x - __bfloat162float(h0));
    __nv_bfloat16 l1 = __float2bfloat16(v.y - __bfloat162float(h1));
    __nv_bfloat16 l2 = __float2bfloat16(v.z - __bfloat162float(h2));
    __nv_bfloat16 l3 = __float2bfloat16(v.w - __bfloat162float(h3));
    uint2 hp, lp;
    hp.x = (uint32_t)__bfloat16_as_ushort(h0) | ((uint32_t)__bfloat16_as_ushort(h1) << 16);
    hp.y = (uint32_t)__bfloat16_as_ushort(h2) | ((uint32_t)__bfloat16_as_ushort(h3) << 16);
    lp.x = (uint32_t)__bfloat16_as_ushort(l0) | ((uint32_t)__bfloat16_as_ushort(l1) << 16);
    lp.y = (uint32_t)__bfloat16_as_ushort(l2) | ((uint32_t)__bfloat16_as_ushort(l3) << 16);
    *(uint2*)(smem + hi_off + row * RSTRIDE + lane * 8) = hp;
    *(uint2*)(smem + lo_off + row * RSTRIDE + lane * 8) = lp;
}

// ---------------- Kernel A: scores = Q K^T (bf16 3-term split) -> scratch ----------------
// M=64 tiles: 1024 CTAs over 148 SMs = 6.92 waves (kills the 3.46->4 wave tail)
#define NT_A 512
#define AQHI 0
#define AQLO 17408
#define AKB(b) (34816 + (b) * 69632)          // K buf b: hi at AKB, lo at +34816
#define SMEM_A 174080

__global__ __launch_bounds__(NT_A, 1)
void scores_kernel(const float* __restrict__ Qg, const float* __restrict__ Kg) {
    extern __shared__ char smem[];
    const uint32_t sb = smem_u32(smem);
    const int tid = threadIdx.x, wid = tid >> 5, lane = tid & 31;
    const int bh = blockIdx.y, q0 = blockIdx.x * QPB;
    const float* Kb = Kg + (size_t)bh * S_LEN * D_DIM;

    // Q split (64 rows): 4 passes x 16 warps
    {
        const float4* src = (const float4*)(Qg + ((size_t)bh * S_LEN + q0) * D_DIM);
        #pragma unroll
        for (int p = 0; p < 4; p++) {
            const int row = p * 16 + wid;
            cvt_store(smem, AQHI, AQLO, row, lane, __ldg(src + (size_t)row * 32 + lane));
        }
    }
    // K tile 0 (128 rows): 8 passes
    {
        #pragma unroll
        for (int p = 0; p < 8; p++) {
            const int row = p * 16 + wid;
            cvt_store(smem, AKB(0), AKB(0) + 34816, row, lane,
                      __ldg((const float4*)Kb + (size_t)row * 32 + lane));
        }
    }
    __syncthreads();

    const int wr = wid & 3, wc = wid >> 2;     // M strip 16*wr, keys [32*wc, 32*wc+32)
    const uint32_t a_off = (uint32_t)((16 * wr + (((lane >> 3) & 1) << 3) + (lane & 7)) * RSTRIDE
                                      + ((lane >> 4) << 4));
    const uint32_t b_off = (uint32_t)((32 * wc + (((lane >> 4) & 1) << 3) + (lane & 7)) * RSTRIDE
                                      + (((lane >> 3) & 1) << 4));
    const int r0 = q0 + 16 * wr + (lane >> 2);
    float* srow0 = g_scores + ((size_t)(bh * S_LEN + r0)) * S_LEN;

    for (int kt = 0; kt < NKT; kt++) {
        float4 pf[8];
        if (kt < NKT - 1) {
            const float4* src = (const float4*)(Kb + (size_t)(kt + 1) * 128 * D_DIM);
            #pragma unroll
            for (int p = 0; p < 8; p++) pf[p] = __ldg(src + (size_t)(p * 16 + wid) * 32 + lane);
        }

        const uint32_t khi = sb + AKB(kt & 1), klo = khi + 34816;
        float acc[4][4];
        #pragma unroll
        for (int n = 0; n < 4; n++)
            #pragma unroll
            for (int r = 0; r < 4; r++) acc[n][r] = 0.f;

        #pragma unroll
        for (int ks = 0; ks < 8; ks++) {
            uint32_t ah[4], al[4];
            ldsm4(ah[0], ah[1], ah[2], ah[3], sb + AQHI + a_off + ks * 32);
            ldsm4(al[0], al[1], al[2], al[3], sb + AQLO + a_off + ks * 32);
            #pragma unroll
            for (int p = 0; p < 2; p++) {
                const uint32_t bo = b_off + (uint32_t)(p * 16 * RSTRIDE + ks * 32);
                uint32_t b0, b1, b2, b3, c0, c1, c2, c3;
                ldsm4(b0, b1, b2, b3, khi + bo);
                ldsm4(c0, c1, c2, c3, klo + bo);
                mma16816(acc[2 * p],     ah, b0, b1);
                mma16816(acc[2 * p + 1], ah, b2, b3);
                mma16816(acc[2 * p],     al, b0, b1);
                mma16816(acc[2 * p + 1], al, b2, b3);
                mma16816(acc[2 * p],     ah, c0, c1);
                mma16816(acc[2 * p + 1], ah, c2, c3);
            }
        }

        const int cb = kt * 128 + 32 * wc + 2 * (lane & 3);
        #pragma unroll
        for (int n = 0; n < 4; n++) {
            *(float2*)(srow0 + cb + 8 * n) = make_float2(acc[n][0], acc[n][1]);
            *(float2*)(srow0 + (size_t)8 * S_LEN + cb + 8 * n) = make_float2(acc[n][2], acc[n][3]);
        }

        if (kt < NKT - 1) {
            const uint32_t dst = AKB((kt + 1) & 1);
            #pragma unroll
            for (int p = 0; p < 8; p++)
                cvt_store(smem, dst, dst + 34816, p * 16 + wid, lane, pf[p]);
        }
        __syncthreads();
    }
}

// ---------------- Kernel B: threshold select (reg-capped for higher occupancy) ----------------
#define NT_B 256
#define BWARPS 8
#define CANDMAX 96

__device__ __forceinline__ unsigned fmono(float f) {
    unsigned u = __float_as_uint(f);
    return u ^ ((unsigned)((int)u >> 31) | 0x80000000u);
}

__global__ __launch_bounds__(NT_B, 6)
void select_kernel(const float* __restrict__ Vg, float* __restrict__ Og) {
    __shared__ uint2    cand_s[BWARPS][CANDMAX];
    __shared__ unsigned fin_s[BWARPS][32];

    const int tid = threadIdx.x, wid = tid >> 5, lane = tid & 31;
    const int q = blockIdx.x * BWARPS + wid;       // global query = bh*2048 + s
    const int bh = q >> 11;
    const unsigned FULL = 0xffffffffu;
    uint2* cand = cand_s[wid];
    unsigned* fin = fin_s[wid];

    const float4* srow4 = (const float4*)(g_scores + (size_t)q * S_LEN);

    // ---- 1. Pass 1: per-lane top-2 values (branchless), no smem copy ----
    float m0 = -FLT_MAX, m1 = -FLT_MAX;
    #pragma unroll
    for (int i = 0; i < 16; i++) {
        float4 v = __ldg(srow4 + i * 32 + lane);
        float t;
        t = fminf(m0, v.x); m0 = fmaxf(m0, v.x); m1 = fmaxf(m1, t);
        t = fminf(m0, v.y); m0 = fmaxf(m0, v.y); m1 = fmaxf(m1, t);
        t = fminf(m0, v.z); m0 = fmaxf(m0, v.z); m1 = fmaxf(m1, t);
        t = fminf(m0, v.w); m0 = fmaxf(m0, v.w); m1 = fmaxf(m1, t);
    }

    // ---- 2. Bitonic sort (descending) of 64 candidates; element i = 2*lane + r ----
    float r0 = m0, r1 = m1;
    #pragma unroll
    for (int k = 2; k <= 64; k <<= 1) {
        #pragma unroll
        for (int j = k >> 1; j >= 1; j >>= 1) {
            const bool desc = (((2 * lane) & k) == 0);
            if (j == 1) {
                float lo = fminf(r0, r1), hi = fmaxf(r0, r1);
                r0 = desc ? hi : lo;
                r1 = desc ? lo : hi;
            } else {
                const int m = j >> 1;
                const float o0 = __shfl_xor_sync(FULL, r0, m);
                const float o1 = __shfl_xor_sync(FULL, r1, m);
                const bool keepMax = (((lane & m) == 0) == desc);
                r0 = keepMax ? fmaxf(r0, o0) : fminf(r0, o0);
                r1 = keepMax ? fmaxf(r1, o1) : fminf(r1, o1);
            }
        }
    }
    const float T1 = __shfl_sync(FULL, r1, 15);    // 32nd largest candidate: count(>=T1) >= 32

    // ---- 3. Pass 2 (L2-hot): inline ballot-compaction of matches ----
    int base = 0;
    #pragma unroll
    for (int i = 0; i < 16; i++) {
        float4 v = __ldg(srow4 + i * 32 + lane);
        const unsigned col = ((unsigned)i << 7) | ((unsigned)lane << 2);
        unsigned bal;
        bal = __ballot_sync(FULL, v.x >= T1);
        if (v.x >= T1) { int o = base + __popc(bal & ((1u << lane) - 1));
                         if (o < CANDMAX) cand[o] = make_uint2(__float_as_uint(v.x), col); }
        base += __popc(bal);
        bal = __ballot_sync(FULL, v.y >= T1);
        if (v.y >= T1) { int o = base + __popc(bal & ((1u << lane) - 1));
                         if (o < CANDMAX) cand[o] = make_uint2(__float_as_uint(v.y), col | 1u); }
        base += __popc(bal);
        bal = __ballot_sync(FULL, v.z >= T1);
        if (v.z >= T1) { int o = base + __popc(bal & ((1u << lane) - 1));
                         if (o < CANDMAX) cand[o] = make_uint2(__float_as_uint(v.z), col | 2u); }
        base += __popc(bal);
        bal = __ballot_sync(FULL, v.w >= T1);
        if (v.w >= T1) { int o = base + __popc(bal & ((1u << lane) - 1));
                         if (o < CANDMAX) cand[o] = make_uint2(__float_as_uint(v.w), col | 3u); }
        base += __popc(bal);
    }
    int c = base < CANDMAX ? base : CANDMAX;       // c >= 32 by construction
    __syncwarp();

    // ---- 4. Trim c-32 smallest (expected ~3 rounds) ----
    float tv[3];
    unsigned alive = 0;
    #pragma unroll
    for (int s = 0; s < 3; s++) {
        const int p = lane + 32 * s;
        if (p < c) { tv[s] = __uint_as_float(cand[p].x); alive |= 1u << s; }
        else tv[s] = FLT_MAX;
    }
    for (int t = c - 32; t > 0; t--) {
        float lm = FLT_MAX; int ls = 0;
        #pragma unroll
        for (int s = 0; s < 3; s++) {
            const bool a = (alive >> s) & 1;
            if (a && tv[s] < lm) { lm = tv[s]; ls = s; }
        }
        const unsigned wmn = __reduce_min_sync(FULL, fmono(lm));
        const unsigned bal = __ballot_sync(FULL, fmono(lm) == wmn);
        if (lane == __ffs(bal) - 1) { alive &= ~(1u << ls); tv[ls] = FLT_MAX; }
    }

    // ---- 5. Repack 32 survivors to lanes 0..31 ----
    int sc = __popc(alive);
    int soff = sc;
    #pragma unroll
    for (int d = 1; d < 32; d <<= 1) {
        int n = __shfl_up_sync(FULL, soff, d);
        if (lane >= d) soff += n;
    }
    soff -= sc;
    #pragma unroll
    for (int s = 0; s < 3; s++) {
        if ((alive >> s) & 1) fin[soff++] = (unsigned)(lane + 32 * s);
    }
    __syncwarp();

    const uint2 ce = cand[fin[lane]];
    const float selv = __uint_as_float(ce.x);
    const unsigned selc = ce.y;

    // ---- 6. Softmax + V gather ----
    float mx = selv;
    #pragma unroll
    for (int o = 16; o; o >>= 1) mx = fmaxf(mx, __shfl_xor_sync(FULL, mx, o));
    const float ex = __expf(selv - mx);
    float s = ex;
    #pragma unroll
    for (int o = 16; o; o >>= 1) s += __shfl_xor_sync(FULL, s, o);
    const float p = ex / s;

    const float* Vb = Vg + (size_t)bh * S_LEN * D_DIM;
    float4 a = make_float4(0.f, 0.f, 0.f, 0.f);
    #pragma unroll 4
    for (int j = 0; j < KTOP; j++) {
        const float    pj = __shfl_sync(FULL, p, j);
        const unsigned cj = __shfl_sync(FULL, selc, j);
        float4 v = __ldg((const float4*)(Vb + (size_t)cj * D_DIM) + lane);
        a.x += pj * v.x; a.y += pj * v.y; a.z += pj * v.z; a.w += pj * v.w;
    }
    ((float4*)(Og + (size_t)q * D_DIM))[lane] = a;
}

extern "C" void kernel_launch(void* const* d_in, const int* in_sizes, int n_in,
                              void* d_out, int out_size) {
    const float* Q = (const float*)d_in[0];
    const float* K = (const float*)d_in[1];
    const float* V = (const float*)d_in[2];
    float* O = (float*)d_out;
    const int BH = in_sizes[0] / (S_LEN * D_DIM);   // 32

    cudaFuncSetAttribute(scores_kernel, cudaFuncAttributeMaxDynamicSharedMemorySize, SMEM_A);

    dim3 gridA(S_LEN / QPB, BH);
    scores_kernel<<<gridA, NT_A, SMEM_A>>>(Q, K);

    const int nq = BH * S_LEN;
    select_kernel<<<nq / BWARPS, NT_B>>>(V, O);
}

// round 15
// speedup vs baseline: 1.2284x; 1.2284x over previous
#include <cuda_runtime.h>
#include <cuda_bf16.h>
#include <cstdint>
#include <cfloat>

#define S_LEN 2048
#define D_DIM 128
#define QPB   128
#define NKT   16
#define KTOP  32
#define RSTRIDE 272        // bf16 tile row stride (17*16B): conflict-free ldmatrix

// 512 MB global scratch for the full score matrix [BH=32][2048][2048] fp32
__device__ float g_scores[(size_t)32 * S_LEN * S_LEN];

__device__ __forceinline__ uint32_t smem_u32(const void* p) {
    uint32_t a;
    asm("{ .reg .u64 t; cvta.to.shared.u64 t, %1; cvt.u32.u64 %0, t; }" : "=r"(a) : "l"(p));
    return a;
}

__device__ __forceinline__ void ldsm4(uint32_t& r0, uint32_t& r1, uint32_t& r2, uint32_t& r3,
                                      uint32_t addr) {
    asm volatile("ldmatrix.sync.aligned.m8n8.x4.shared.b16 {%0,%1,%2,%3}, [%4];"
                 : "=r"(r0), "=r"(r1), "=r"(r2), "=r"(r3) : "r"(addr));
}

__device__ __forceinline__ void mma16816(float* c, const uint32_t* a, uint32_t b0, uint32_t b1) {
    asm volatile(
        "mma.sync.aligned.m16n8k16.row.col.f32.bf16.bf16.f32 "
        "{%0,%1,%2,%3}, {%4,%5,%6,%7}, {%8,%9}, {%0,%1,%2,%3};"
        : "+f"(c[0]), "+f"(c[1]), "+f"(c[2]), "+f"(c[3])
        : "r"(a[0]), "r"(a[1]), "r"(a[2]), "r"(a[3]), "r"(b0), "r"(b1));
}

__device__ __forceinline__ void cvt_store(char* smem, uint32_t hi_off, uint32_t lo_off,
                                          int row, int lane, float4 v) {
    __nv_bfloat16 h0 = __float2bfloat16(v.x), h1 = __float2bfloat16(v.y);
    __nv_bfloat16 h2 = __float2bfloat16(v.z), h3 = __float2bfloat16(v.w);
    __nv_bfloat16 l0 = __float2bfloat16(v.x - __bfloat162float(h0));
    __nv_bfloat16 l1 = __float2bfloat16(v.y - __bfloat162float(h1));
    __nv_bfloat16 l2 = __float2bfloat16(v.z - __bfloat162float(h2));
    __nv_bfloat16 l3 = __float2bfloat16(v.w - __bfloat162float(h3));
    uint2 hp, lp;
    hp.x = (uint32_t)__bfloat16_as_ushort(h0) | ((uint32_t)__bfloat16_as_ushort(h1) << 16);
    hp.y = (uint32_t)__bfloat16_as_ushort(h2) | ((uint32_t)__bfloat16_as_ushort(h3) << 16);
    lp.x = (uint32_t)__bfloat16_as_ushort(l0) | ((uint32_t)__bfloat16_as_ushort(l1) << 16);
    lp.y = (uint32_t)__bfloat16_as_ushort(l2) | ((uint32_t)__bfloat16_as_ushort(l3) << 16);
    *(uint2*)(smem + hi_off + row * RSTRIDE + lane * 8) = hp;
    *(uint2*)(smem + lo_off + row * RSTRIDE + lane * 8) = lp;
}

// ---------------- Kernel A: scores = Q K^T (bf16 3-term split) -> scratch ----------------
// (R12 verbatim apart from bh_base: measured at the legacy-HMMA pipe floor, ~349us)
#define NT_A 512
#define AQHI 0
#define AQLO 34816
#define AKB(b) (69632 + (b) * 69632)
#define SMEM_A (69632 * 3)                    // 208896

__global__ __launch_bounds__(NT_A, 1)
void scores_kernel(const float* __restrict__ Qg, const float* __restrict__ Kg, int bh_base) {
    extern __shared__ char smem[];
    const uint32_t sb = smem_u32(smem);
    const int tid = threadIdx.x, wid = tid >> 5, lane = tid & 31;
    const int bh = bh_base + blockIdx.y, q0 = blockIdx.x * QPB;
    const float* Kb = Kg + (size_t)bh * S_LEN * D_DIM;

    {
        const float4* src = (const float4*)(Qg + ((size_t)bh * S_LEN + q0) * D_DIM);
        #pragma unroll
        for (int p = 0; p < 8; p++) {
            const int row = p * 16 + wid;
            cvt_store(smem, AQHI, AQLO, row, lane, __ldg(src + (size_t)row * 32 + lane));
        }
    }
    {
        #pragma unroll
        for (int p = 0; p < 8; p++) {
            const int row = p * 16 + wid;
            cvt_store(smem, AKB(0), AKB(0) + 34816, row, lane,
                      __ldg((const float4*)Kb + (size_t)row * 32 + lane));
        }
    }
    __syncthreads();

    const int wr = wid & 7, wc = wid >> 3;
    const uint32_t a_off = (uint32_t)((16 * wr + (((lane >> 3) & 1) << 3) + (lane & 7)) * RSTRIDE
                                      + ((lane >> 4) << 4));
    const uint32_t b_off = (uint32_t)((64 * wc + (((lane >> 4) & 1) << 3) + (lane & 7)) * RSTRIDE
                                      + (((lane >> 3) & 1) << 4));
    const int r0 = q0 + 16 * wr + (lane >> 2);
    float* srow0 = g_scores + ((size_t)(bh * S_LEN + r0)) * S_LEN;

    for (int kt = 0; kt < NKT; kt++) {
        float4 pf[8];
        if (kt < NKT - 1) {
            const float4* src = (const float4*)(Kb + (size_t)(kt + 1) * 128 * D_DIM);
            #pragma unroll
            for (int p = 0; p < 8; p++) pf[p] = __ldg(src + (size_t)(p * 16 + wid) * 32 + lane);
        }

        const uint32_t khi = sb + AKB(kt & 1), klo = khi + 34816;
        float acc[8][4];
        #pragma unroll
        for (int n = 0; n < 8; n++)
            #pragma unroll
            for (int r = 0; r < 4; r++) acc[n][r] = 0.f;

        #pragma unroll
        for (int ks = 0; ks < 8; ks++) {
            uint32_t ah[4], al[4];
            ldsm4(ah[0], ah[1], ah[2], ah[3], sb + AQHI + a_off + ks * 32);
            ldsm4(al[0], al[1], al[2], al[3], sb + AQLO + a_off + ks * 32);
            #pragma unroll
            for (int p = 0; p < 4; p++) {
                const uint32_t bo = b_off + (uint32_t)(p * 16 * RSTRIDE + ks * 32);
                uint32_t b0, b1, b2, b3, c0, c1, c2, c3;
                ldsm4(b0, b1, b2, b3, khi + bo);
                ldsm4(c0, c1, c2, c3, klo + bo);
                mma16816(acc[2 * p],     ah, b0, b1);
                mma16816(acc[2 * p + 1], ah, b2, b3);
                mma16816(acc[2 * p],     al, b0, b1);
                mma16816(acc[2 * p + 1], al, b2, b3);
                mma16816(acc[2 * p],     ah, c0, c1);
                mma16816(acc[2 * p + 1], ah, c2, c3);
            }
        }

        const int cb = kt * 128 + 64 * wc + 2 * (lane & 3);
        #pragma unroll
        for (int n = 0; n < 8; n++) {
            *(float2*)(srow0 + cb + 8 * n) = make_float2(acc[n][0], acc[n][1]);
            *(float2*)(srow0 + (size_t)8 * S_LEN + cb + 8 * n) = make_float2(acc[n][2], acc[n][3]);
        }

        if (kt < NKT - 1) {
            const uint32_t dst = AKB((kt + 1) & 1);
            #pragma unroll
            for (int p = 0; p < 8; p++)
                cvt_store(smem, dst, dst + 34816, p * 16 + wid, lane, pf[p]);
        }
        __syncthreads();
    }
}

// ---------------- Kernel B: threshold select (R12 verbatim + qbase) ----------------
#define NT_B 256
#define BWARPS 8
#define CANDMAX 96

__device__ __forceinline__ unsigned fmono(float f) {
    unsigned u = __float_as_uint(f);
    return u ^ ((unsigned)((int)u >> 31) | 0x80000000u);
}

__global__ __launch_bounds__(NT_B, 4)
void select_kernel(const float* __restrict__ Vg, float* __restrict__ Og, int qbase) {
    __shared__ uint2    cand_s[BWARPS][CANDMAX];
    __shared__ unsigned fin_s[BWARPS][32];

    const int tid = threadIdx.x, wid = tid >> 5, lane = tid & 31;
    const int q = qbase + blockIdx.x * BWARPS + wid;   // global query = bh*2048 + s
    const int bh = q >> 11;
    const unsigned FULL = 0xffffffffu;
    uint2* cand = cand_s[wid];
    unsigned* fin = fin_s[wid];

    const float4* srow4 = (const float4*)(g_scores + (size_t)q * S_LEN);

    // ---- 1. Pass 1: per-lane top-2 values (branchless), no smem copy ----
    float m0 = -FLT_MAX, m1 = -FLT_MAX;
    #pragma unroll
    for (int i = 0; i < 16; i++) {
        float4 v = __ldg(srow4 + i * 32 + lane);
        float t;
        t = fminf(m0, v.x); m0 = fmaxf(m0, v.x); m1 = fmaxf(m1, t);
        t = fminf(m0, v.y); m0 = fmaxf(m0, v.y); m1 = fmaxf(m1, t);
        t = fminf(m0, v.z); m0 = fmaxf(m0, v.z); m1 = fmaxf(m1, t);
        t = fminf(m0, v.w); m0 = fmaxf(m0, v.w); m1 = fmaxf(m1, t);
    }

    // ---- 2. Bitonic sort (descending) of 64 candidates; element i = 2*lane + r ----
    float r0 = m0, r1 = m1;
    #pragma unroll
    for (int k = 2; k <= 64; k <<= 1) {
        #pragma unroll
        for (int j = k >> 1; j >= 1; j >>= 1) {
            const bool desc = (((2 * lane) & k) == 0);
            if (j == 1) {
                float lo = fminf(r0, r1), hi = fmaxf(r0, r1);
                r0 = desc ? hi : lo;
                r1 = desc ? lo : hi;
            } else {
                const int m = j >> 1;
                const float o0 = __shfl_xor_sync(FULL, r0, m);
                const float o1 = __shfl_xor_sync(FULL, r1, m);
                const bool keepMax = (((lane & m) == 0) == desc);
                r0 = keepMax ? fmaxf(r0, o0) : fminf(r0, o0);
                r1 = keepMax ? fmaxf(r1, o1) : fminf(r1, o1);
            }
        }
    }
    const float T1 = __shfl_sync(FULL, r1, 15);    // 32nd largest candidate: count(>=T1) >= 32

    // ---- 3. Pass 2 (L2-hot): inline ballot-compaction of matches ----
    int base = 0;
    #pragma unroll
    for (int i = 0; i < 16; i++) {
        float4 v = __ldg(srow4 + i * 32 + lane);
        const unsigned col = ((unsigned)i << 7) | ((unsigned)lane << 2);
        unsigned bal;
        bal = __ballot_sync(FULL, v.x >= T1);
        if (v.x >= T1) { int o = base + __popc(bal & ((1u << lane) - 1));
                         if (o < CANDMAX) cand[o] = make_uint2(__float_as_uint(v.x), col); }
        base += __popc(bal);
        bal = __ballot_sync(FULL, v.y >= T1);
        if (v.y >= T1) { int o = base + __popc(bal & ((1u << lane) - 1));
                         if (o < CANDMAX) cand[o] = make_uint2(__float_as_uint(v.y), col | 1u); }
        base += __popc(bal);
        bal = __ballot_sync(FULL, v.z >= T1);
        if (v.z >= T1) { int o = base + __popc(bal & ((1u << lane) - 1));
                         if (o < CANDMAX) cand[o] = make_uint2(__float_as_uint(v.z), col | 2u); }
        base += __popc(bal);
        bal = __ballot_sync(FULL, v.w >= T1);
        if (v.w >= T1) { int o = base + __popc(bal & ((1u << lane) - 1));
                         if (o < CANDMAX) cand[o] = make_uint2(__float_as_uint(v.w), col | 3u); }
        base += __popc(bal);
    }
    int c = base < CANDMAX ? base : CANDMAX;       // c >= 32 by construction
    __syncwarp();

    // ---- 4. Trim c-32 smallest (expected ~3 rounds) ----
    float tv[3];
    unsigned alive = 0;
    #pragma unroll
    for (int s = 0; s < 3; s++) {
        const int p = lane + 32 * s;
        if (p < c) { tv[s] = __uint_as_float(cand[p].x); alive |= 1u << s; }
        else tv[s] = FLT_MAX;
    }
    for (int t = c - 32; t > 0; t--) {
        float lm = FLT_MAX; int ls = 0;
        #pragma unroll
        for (int s = 0; s < 3; s++) {
            const bool a = (alive >> s) & 1;
            if (a && tv[s] < lm) { lm = tv[s]; ls = s; }
        }
        const unsigned wmn = __reduce_min_sync(FULL, fmono(lm));
        const unsigned bal = __ballot_sync(FULL, fmono(lm) == wmn);
        if (lane == __ffs(bal) - 1) { alive &= ~(1u << ls); tv[ls] = FLT_MAX; }
    }

    // ---- 5. Repack 32 survivors to lanes 0..31 ----
    int sc = __popc(alive);
    int soff = sc;
    #pragma unroll
    for (int d = 1; d < 32; d <<= 1) {
        int n = __shfl_up_sync(FULL, soff, d);
        if (lane >= d) soff += n;
    }
    soff -= sc;
    #pragma unroll
    for (int s = 0; s < 3; s++) {
        if ((alive >> s) & 1) fin[soff++] = (unsigned)(lane + 32 * s);
    }
    __syncwarp();

    const uint2 ce = cand[fin[lane]];
    const float selv = __uint_as_float(ce.x);
    const unsigned selc = ce.y;

    // ---- 6. Softmax + V gather ----
    float mx = selv;
    #pragma unroll
    for (int o = 16; o; o >>= 1) mx = fmaxf(mx, __shfl_xor_sync(FULL, mx, o));
    const float ex = __expf(selv - mx);
    float s = ex;
    #pragma unroll
    for (int o = 16; o; o >>= 1) s += __shfl_xor_sync(FULL, s, o);
    const float p = ex / s;

    const float* Vb = Vg + (size_t)bh * S_LEN * D_DIM;
    float4 a = make_float4(0.f, 0.f, 0.f, 0.f);
    #pragma unroll 4
    for (int j = 0; j < KTOP; j++) {
        const float    pj = __shfl_sync(FULL, p, j);
        const unsigned cj = __shfl_sync(FULL, selc, j);
        float4 v = __ldg((const float4*)(Vb + (size_t)cj * D_DIM) + lane);
        a.x += pj * v.x; a.y += pj * v.y; a.z += pj * v.z; a.w += pj * v.w;
    }
    ((float4*)(Og + (size_t)q * D_DIM))[lane] = a;
}

// ---------------- Launcher: scores chunks alternate on sA/sB (dense backfill);
// select chunk c on sC after chunk c's scores event. Kernels = R12 verbatim. ----
#define NCHUNK 4

extern "C" void kernel_launch(void* const* d_in, const int* in_sizes, int n_in,
                              void* d_out, int out_size) {
    const float* Q = (const float*)d_in[0];
    const float* K = (const float*)d_in[1];
    const float* V = (const float*)d_in[2];
    float* O = (float*)d_out;
    const int BH = in_sizes[0] / (S_LEN * D_DIM);   // 32

    static bool init_done = false;
    static cudaStream_t sA, sB, sC;
    static cudaEvent_t evRoot, evS[NCHUNK], evEA, evEB, evEC;
    if (!init_done) {   // first call is the uncaptured correctness run
        cudaStreamCreateWithFlags(&sA, cudaStreamNonBlocking);
        cudaStreamCreateWithFlags(&sB, cudaStreamNonBlocking);
        cudaStreamCreateWithFlags(&sC, cudaStreamNonBlocking);
        cudaEventCreateWithFlags(&evRoot, cudaEventDisableTiming);
        for (int c = 0; c < NCHUNK; c++) cudaEventCreateWithFlags(&evS[c], cudaEventDisableTiming);
        cudaEventCreateWithFlags(&evEA, cudaEventDisableTiming);
        cudaEventCreateWithFlags(&evEB, cudaEventDisableTiming);
        cudaEventCreateWithFlags(&evEC, cudaEventDisableTiming);
        cudaFuncSetAttribute(scores_kernel, cudaFuncAttributeMaxDynamicSharedMemorySize, SMEM_A);
        init_done = true;
    }

    if (BH % NCHUNK == 0) {
        const int bhpc = BH / NCHUNK;                  // 8
        const int qpc  = bhpc * S_LEN;                 // 16384
        cudaEventRecord(evRoot, 0);
        cudaStreamWaitEvent(sA, evRoot, 0);
        cudaStreamWaitEvent(sB, evRoot, 0);
        for (int c = 0; c < NCHUNK; c++) {
            cudaStream_t ss = (c & 1) ? sB : sA;
            dim3 gA(S_LEN / QPB, bhpc);
            scores_kernel<<<gA, NT_A, SMEM_A, ss>>>(Q, K, c * bhpc);
            cudaEventRecord(evS[c], ss);
            cudaStreamWaitEvent(sC, evS[c], 0);
            select_kernel<<<qpc / BWARPS, NT_B, 0, sC>>>(V, O, c * qpc);
        }
        cudaEventRecord(evEA, sA);
        cudaEventRecord(evEB, sB);
        cudaEventRecord(evEC, sC);
        cudaStreamWaitEvent(0, evEA, 0);
        cudaStreamWaitEvent(0, evEB, 0);
        cudaStreamWaitEvent(0, evEC, 0);
    } else {
        dim3 gA(S_LEN / QPB, BH);
        scores_kernel<<<gA, NT_A, SMEM_A, 0>>>(Q, K, 0);
        select_kernel<<<BH * S_LEN / BWARPS, NT_B, 0, 0>>>(V, O, 0);
    }
}